// round 3
// baseline (speedup 1.0000x reference)
#include <cuda_runtime.h>
#include <cuda_bf16.h>

// Problem constants (fixed by the dataset)
#define BB 4
#define CC 144
#define NN 16384
#define KK 16
#define GG 9
#define DD 16   // CC / GG

// Scratch: transposed (B,G,N,d) copies of queryandkey and value.
// 2 x 4*144*16384 floats = 75.5 MB static device memory (allowed).
__device__ float g_qkT[BB * CC * NN];
__device__ float g_vT[BB * CC * NN];

// ---------------------------------------------------------------------------
// Kernel 1: transpose (B, C=G*d, N) -> (B, G, N, d) for both input arrays.
// Tile: 16 d x 64 n per (b,g). Coalesced loads and stores via smem.
// tile indexed [n][d] with d-stride 17 -> both phases bank-conflict-free.
// ---------------------------------------------------------------------------
__global__ __launch_bounds__(256) void transpose_kernel(
    const float* __restrict__ qk, const float* __restrict__ val)
{
    __shared__ float tile[2][64][17];  // [arr][n][d], padded d-stride

    const int b = blockIdx.z;
    const int g = blockIdx.y;
    const int n_base = blockIdx.x * 64;
    const int t = threadIdx.x;

    // Load phase: rows of 64 contiguous floats (256B segments), both arrays.
    // Write tile[n][d]: lane i -> n = i&63 distinct; addr 17*n + d,
    // banks (17*n) mod 32 distinct over any 32 consecutive n (17 odd).
    #pragma unroll
    for (int r = 0; r < 4; r++) {
        int j = t + r * 256;
        int d = j >> 6;
        int n = j & 63;
        int src_off = (b * CC + g * DD + d) * NN + n_base + n;
        tile[0][n][d] = qk[src_off];
        tile[1][n][d] = val[src_off];
    }
    __syncthreads();

    // Store phase: d-contiguous (16 floats per n), fully coalesced gmem.
    // Read tile[n][d]: lane i -> d = i&15, n differs by 1 across warp halves:
    // bank sets {d} and {(17+d) mod 32} are disjoint -> conflict-free.
    #pragma unroll
    for (int r = 0; r < 4; r++) {
        int j = t + r * 256;
        int n = j >> 4;
        int d = j & 15;
        int dst_off = (((b * GG + g) * NN + n_base + n) << 4) + d;
        g_qkT[dst_off] = tile[0][n][d];
        g_vT[dst_off]  = tile[1][n][d];
    }
}

// ---------------------------------------------------------------------------
// Kernel 2: fused gather + attention + softmax + centrality + aggregation.
// One warp per n. Lane = (k = lane>>1, h = lane&1); h selects dims [8h, 8h+8).
// Block = 512 threads = 16 warps = 16 consecutive n for one (b,g).
// ---------------------------------------------------------------------------
__global__ __launch_bounds__(512) void attn_kernel(
    const int* __restrict__ idx,
    float* __restrict__ feat,   // (B, C, N)
    float* __restrict__ cent)   // (B, G, N), pre-zeroed
{
    __shared__ float sfeat[DD][17];  // [d][n_in_block], padded

    const int b    = blockIdx.z;
    const int g    = blockIdx.y;
    const int wid  = threadIdx.x >> 5;
    const int lane = threadIdx.x & 31;
    const int n    = blockIdx.x * 16 + wid;
    const int k    = lane >> 1;
    const int h    = lane & 1;

    const int bg   = b * GG + g;
    const int bg_base = bg * (NN * DD);
    const float* __restrict__ qk_bg = g_qkT + bg_base;
    const float* __restrict__ v_bg  = g_vT + bg_base;
    float* __restrict__ cent_bg = cent + bg * NN;

    // --- q for this n (same-h lanes read the same 32B: L1 broadcast)
    const float4* qp = reinterpret_cast<const float4*>(qk_bg + n * DD + h * 8);
    float4 q0 = qp[0];
    float4 q1 = qp[1];

    // --- neighbor index (one 64B line per warp, pair-duplicated)
    int j = idx[(b * NN + n) * KK + k];

    // --- gather key (2 independent float4 = 32B, a full sector per lane)
    const float4* kp = reinterpret_cast<const float4*>(qk_bg + j * DD + h * 8);
    float4 k0 = kp[0];
    float4 k1 = kp[1];
    // --- gather value
    const float4* vp = reinterpret_cast<const float4*>(v_bg + j * DD + h * 8);
    float4 v0 = vp[0];
    float4 v1 = vp[1];

    // --- partial dot over 8 dims, then combine the (h=0, h=1) halves
    float dot = q0.x * k0.x + q0.y * k0.y + q0.z * k0.z + q0.w * k0.w
              + q1.x * k1.x + q1.y * k1.y + q1.z * k1.z + q1.w * k1.w;
    dot += __shfl_xor_sync(0xffffffffu, dot, 1);
    // Lanes 2k and 2k+1 both hold logit_k.

    // --- softmax over the 16 distinct k (masks 2..16 keep pair duplication)
    float m = dot;
    #pragma unroll
    for (int msk = 2; msk < 32; msk <<= 1)
        m = fmaxf(m, __shfl_xor_sync(0xffffffffu, m, msk));
    float e = __expf(dot - m);
    float s = e;
    #pragma unroll
    for (int msk = 2; msk < 32; msk <<= 1)
        s += __shfl_xor_sync(0xffffffffu, s, msk);
    float att = e / s;

    // --- centrality scatter: exactly one RED.ADD per (n, k)
    if (h == 0)
        atomicAdd(cent_bg + j, att);

    // --- weighted value aggregation: reduce over k (same-h lanes)
    float a0x = att * v0.x, a0y = att * v0.y, a0z = att * v0.z, a0w = att * v0.w;
    float a1x = att * v1.x, a1y = att * v1.y, a1z = att * v1.z, a1w = att * v1.w;
    #pragma unroll
    for (int msk = 2; msk < 32; msk <<= 1) {
        a0x += __shfl_xor_sync(0xffffffffu, a0x, msk);
        a0y += __shfl_xor_sync(0xffffffffu, a0y, msk);
        a0z += __shfl_xor_sync(0xffffffffu, a0z, msk);
        a0w += __shfl_xor_sync(0xffffffffu, a0w, msk);
        a1x += __shfl_xor_sync(0xffffffffu, a1x, msk);
        a1y += __shfl_xor_sync(0xffffffffu, a1y, msk);
        a1z += __shfl_xor_sync(0xffffffffu, a1z, msk);
        a1w += __shfl_xor_sync(0xffffffffu, a1w, msk);
    }

    // Lanes 0 (h=0) and 1 (h=1) of each warp hold the final feat[d] halves.
    if (k == 0) {
        int d0 = h * 8;
        sfeat[d0 + 0][wid] = a0x;
        sfeat[d0 + 1][wid] = a0y;
        sfeat[d0 + 2][wid] = a0z;
        sfeat[d0 + 3][wid] = a0w;
        sfeat[d0 + 4][wid] = a1x;
        sfeat[d0 + 5][wid] = a1y;
        sfeat[d0 + 6][wid] = a1z;
        sfeat[d0 + 7][wid] = a1w;
    }
    __syncthreads();

    // --- coalesced writeback to (B, C, N): 64B contiguous per d-row
    if (threadIdx.x < 256) {
        int d = threadIdx.x >> 4;
        int w = threadIdx.x & 15;
        feat[(b * CC + g * DD + d) * NN + blockIdx.x * 16 + w] = sfeat[d][w];
    }
}

// ---------------------------------------------------------------------------
// Launch: memset(cent) -> transpose -> fused attention. All on stream 0,
// graph-capturable, no allocations.
// ---------------------------------------------------------------------------
extern "C" void kernel_launch(void* const* d_in, const int* in_sizes, int n_in,
                              void* d_out, int out_size)
{
    const float* qk  = (const float*)d_in[0];  // queryandkey (B,C,N) fp32
    const float* val = (const float*)d_in[1];  // value       (B,C,N) fp32
    const int*   idx = (const int*)d_in[2];    // idx_knn     (B,N,K) int32

    float* feat = (float*)d_out;               // (B,C,N)
    float* cent = feat + (size_t)BB * CC * NN; // (B,G,N)

    // cent is accumulated with atomics; output buffer is poisoned -> zero it.
    cudaMemsetAsync(cent, 0, (size_t)BB * GG * NN * sizeof(float), 0);

    {
        dim3 grid(NN / 64, GG, BB);
        transpose_kernel<<<grid, 256, 0, 0>>>(qk, val);
    }
    {
        dim3 grid(NN / 16, GG, BB);
        attn_kernel<<<grid, 512, 0, 0>>>(idx, feat, cent);
    }
}

// round 6
// speedup vs baseline: 1.4080x; 1.4080x over previous
#include <cuda_runtime.h>
#include <cuda_bf16.h>

// Problem constants (fixed by the dataset)
#define BB 4
#define CC 144
#define NN 16384
#define KK 16
#define GG 9
#define DD 16   // CC / GG

// Scratch: interleaved (B,G,N,{key[16],value[16]}) layout.
// One neighbor = 32 floats = exactly one 128B cache line.
// 4*9*16384*32 floats = 75.5 MB static device memory (allowed).
__device__ float g_kv[BB * GG * NN * 32];

// ---------------------------------------------------------------------------
// Kernel 1: transpose (B, C=G*d, N) -> interleaved kv[(b,g,n)*32 + {d | 16+d}].
// Tile: 16 d x 64 n per (b,g). Coalesced loads; 64B-chunked stores.
// ---------------------------------------------------------------------------
__global__ __launch_bounds__(256) void transpose_kernel(
    const float* __restrict__ qk, const float* __restrict__ val)
{
    __shared__ float tile[2][64][17];  // [arr][n][d], padded d-stride

    const int b = blockIdx.z;
    const int g = blockIdx.y;
    const int n_base = blockIdx.x * 64;
    const int t = threadIdx.x;

    // Load phase: rows of 64 contiguous floats (256B segments), both arrays.
    #pragma unroll
    for (int r = 0; r < 4; r++) {
        int j = t + r * 256;
        int d = j >> 6;
        int n = j & 63;
        int src_off = (b * CC + g * DD + d) * NN + n_base + n;
        tile[0][n][d] = qk[src_off];
        tile[1][n][d] = val[src_off];
    }
    __syncthreads();

    // Store phase: per n, key floats at +0..15, value floats at +16..31.
    // Each 128B kv line is fully written by two 64B-coalesced stores.
    #pragma unroll
    for (int r = 0; r < 4; r++) {
        int j = t + r * 256;
        int n = j >> 4;
        int d = j & 15;
        int dst = (((b * GG + g) * NN + n_base + n) << 5);
        g_kv[dst + d]      = tile[0][n][d];
        g_kv[dst + 16 + d] = tile[1][n][d];
    }
}

// ---------------------------------------------------------------------------
// Kernel 2: fused gather + attention + softmax + centrality + aggregation.
// One warp per n. Lane = (jj = lane>>3, c = lane&7).
// Iteration it gathers neighbors j = it*4 + jj; the 8 lanes of a jj-group
// cover that neighbor's full 128B line (c*16B each): 4 lines / instruction
// = the L1TEX wavefront floor.
//   c in 0..3 : key chunk c   (dims c*4 .. c*4+3)  -> dot partials
//   c in 4..7 : value chunk c-4                    -> att-weighted accumulate
// Block = 512 threads = 16 warps = 16 consecutive n for one (b,g).
// ---------------------------------------------------------------------------
__global__ __launch_bounds__(512) void attn_kernel(
    const int* __restrict__ idx,
    float* __restrict__ feat,   // (B, C, N)
    float* __restrict__ cent)   // (B, G, N), pre-zeroed
{
    __shared__ float sfeat[DD][17];  // [d][n_in_block], padded

    const unsigned FULL = 0xffffffffu;
    const int b    = blockIdx.z;
    const int g    = blockIdx.y;
    const int wid  = threadIdx.x >> 5;
    const int lane = threadIdx.x & 31;
    const int n    = blockIdx.x * 16 + wid;
    const int jj   = lane >> 3;   // neighbor sub-group 0..3
    const int c    = lane & 7;    // 16B chunk within the 128B kv line
    const int cc   = lane & 3;

    const int bg = b * GG + g;
    const float4* __restrict__ kv_bg =
        reinterpret_cast<const float4*>(g_kv) + (size_t)bg * NN * 8;
    float* __restrict__ cent_bg = cent + bg * NN;

    // q chunk cc for this n (all jj-groups same address: L1 broadcast)
    float4 q = kv_bg[n * 8 + cc];

    // neighbor indices: one 64B line per warp (lanes 16..31 duplicate)
    int myidx = idx[(b * NN + n) * KK + (lane & 15)];

    float  lg[4];
    float4 v[4];
    int    jreg[4];

    #pragma unroll
    for (int it = 0; it < 4; it++) {
        int j = __shfl_sync(FULL, myidx, it * 4 + jj);
        jreg[it] = j;
        // One LDG.128 covering 4 full neighbor lines across the warp.
        float4 dv = kv_bg[j * 8 + c];
        v[it] = dv;
        // dot partial (meaningful on key lanes c<4; junk on value lanes)
        float p = q.x * dv.x + q.y * dv.y + q.z * dv.z + q.w * dv.w;
        p += __shfl_xor_sync(FULL, p, 1);
        p += __shfl_xor_sync(FULL, p, 2);
        // broadcast the key-lane result (same jj, c mod 4) to all 8 lanes
        lg[it] = __shfl_sync(FULL, p, lane & 27);
    }

    // --- softmax over the 16 neighbors: 4 local + cross-jj (masks 8,16)
    float m = fmaxf(fmaxf(lg[0], lg[1]), fmaxf(lg[2], lg[3]));
    m = fmaxf(m, __shfl_xor_sync(FULL, m, 8));
    m = fmaxf(m, __shfl_xor_sync(FULL, m, 16));
    float e0 = __expf(lg[0] - m);
    float e1 = __expf(lg[1] - m);
    float e2 = __expf(lg[2] - m);
    float e3 = __expf(lg[3] - m);
    float s = e0 + e1 + e2 + e3;
    s += __shfl_xor_sync(FULL, s, 8);
    s += __shfl_xor_sync(FULL, s, 16);
    float inv = __frcp_rn(s);
    float a0 = e0 * inv, a1 = e1 * inv, a2 = e2 * inv, a3 = e3 * inv;

    // --- centrality scatter: lane c==0 of each jj-group, 4 REDG each
    if (c == 0) {
        atomicAdd(cent_bg + jreg[0], a0);
        atomicAdd(cent_bg + jreg[1], a1);
        atomicAdd(cent_bg + jreg[2], a2);
        atomicAdd(cent_bg + jreg[3], a3);
    }

    // --- weighted value accumulation (meaningful on value lanes c>=4)
    float4 acc;
    acc.x = a0 * v[0].x + a1 * v[1].x + a2 * v[2].x + a3 * v[3].x;
    acc.y = a0 * v[0].y + a1 * v[1].y + a2 * v[2].y + a3 * v[3].y;
    acc.z = a0 * v[0].z + a1 * v[1].z + a2 * v[2].z + a3 * v[3].z;
    acc.w = a0 * v[0].w + a1 * v[1].w + a2 * v[2].w + a3 * v[3].w;
    // reduce across jj groups (masks 8,16 keep c fixed)
    acc.x += __shfl_xor_sync(FULL, acc.x, 8);
    acc.y += __shfl_xor_sync(FULL, acc.y, 8);
    acc.z += __shfl_xor_sync(FULL, acc.z, 8);
    acc.w += __shfl_xor_sync(FULL, acc.w, 8);
    acc.x += __shfl_xor_sync(FULL, acc.x, 16);
    acc.y += __shfl_xor_sync(FULL, acc.y, 16);
    acc.z += __shfl_xor_sync(FULL, acc.z, 16);
    acc.w += __shfl_xor_sync(FULL, acc.w, 16);

    // lanes (jj==0, c=4..7) hold final feat chunks d = (c-4)*4 + {0..3}
    if (jj == 0 && c >= 4) {
        int d0 = (c - 4) * 4;
        sfeat[d0 + 0][wid] = acc.x;
        sfeat[d0 + 1][wid] = acc.y;
        sfeat[d0 + 2][wid] = acc.z;
        sfeat[d0 + 3][wid] = acc.w;
    }
    __syncthreads();

    // --- coalesced writeback to (B, C, N): 64B contiguous per d-row
    if (threadIdx.x < 256) {
        int d = threadIdx.x >> 4;
        int w = threadIdx.x & 15;
        feat[(b * CC + g * DD + d) * NN + blockIdx.x * 16 + w] = sfeat[d][w];
    }
}

// ---------------------------------------------------------------------------
// Launch: memset(cent) -> transpose -> fused attention. All on stream 0,
// graph-capturable, no allocations.
// ---------------------------------------------------------------------------
extern "C" void kernel_launch(void* const* d_in, const int* in_sizes, int n_in,
                              void* d_out, int out_size)
{
    const float* qk  = (const float*)d_in[0];  // queryandkey (B,C,N) fp32
    const float* val = (const float*)d_in[1];  // value       (B,C,N) fp32
    const int*   idx = (const int*)d_in[2];    // idx_knn     (B,N,K) int32

    float* feat = (float*)d_out;               // (B,C,N)
    float* cent = feat + (size_t)BB * CC * NN; // (B,G,N)

    // cent is accumulated with atomics; output buffer is poisoned -> zero it.
    cudaMemsetAsync(cent, 0, (size_t)BB * GG * NN * sizeof(float), 0);

    {
        dim3 grid(NN / 64, GG, BB);
        transpose_kernel<<<grid, 256, 0, 0>>>(qk, val);
    }
    {
        dim3 grid(NN / 16, GG, BB);
        attn_kernel<<<grid, 512, 0, 0>>>(idx, feat, cent);
    }
}